// round 2
// baseline (speedup 1.0000x reference)
#include <cuda_runtime.h>

// Problem constants (fixed shapes)
#define U      1024
#define BATCH  4
#define NCHAN  2
#define TLEN   1024
#define HEADS  8
#define DK     128
#define MROWS  (BATCH * NCHAN * TLEN)   // 8192

// Scratch (device globals — allocation-free per harness rules)
__device__ float g_Q[(size_t)MROWS * U];
__device__ float g_K[(size_t)MROWS * U];
__device__ float g_V[(size_t)MROWS * U];
__device__ float g_att[(size_t)BATCH * HEADS * TLEN * TLEN];  // [b*8+h][t][s]
__device__ float g_ao[(size_t)MROWS * U];

// ---------------- Tiled SGEMM core: 128x128 block, 8x8/thread, BK=8 --------
#define BM 128
#define BN 128
#define BK 8
#define TM 8
#define TN 8
// 256 threads/block

// NT=true : C[m,n] = alpha * sum_k A[m,k]*B[n,k]  (B row-major [N,K])
// NT=false: C[m,n] = alpha * sum_k A[m,k]*B[k,n]  (B row-major [K,N])
template <bool NT>
__device__ __forceinline__ void gemm_body(
    const float* __restrict__ A, int lda,
    const float* __restrict__ B, int ldb,
    float* __restrict__ C, int ldc,
    int K, float alpha, const float* __restrict__ bias)
{
    __shared__ float As[BK][BM];
    __shared__ float Bs[BK][BN];

    const int tid  = threadIdx.x;
    const int tx   = tid & 15;        // 0..15  -> N
    const int ty   = tid >> 4;        // 0..15  -> M
    const int arow = tid >> 1;        // 0..127
    const int acol = (tid & 1) << 2;  // 0 or 4
    const int brow = tid >> 5;        // 0..7   (NN loader)
    const int bcol = (tid & 31) << 2; // 0..124 (NN loader)

    const float* Ab = A + (size_t)blockIdx.y * BM * lda;
    const float* Bb = NT ? (B + (size_t)blockIdx.x * BN * ldb)
                         : (B + (size_t)blockIdx.x * BN);

    float acc[TM][TN] = {};

    for (int k0 = 0; k0 < K; k0 += BK) {
        float4 av = *(const float4*)(Ab + (size_t)arow * lda + k0 + acol);
        As[acol + 0][arow] = av.x;
        As[acol + 1][arow] = av.y;
        As[acol + 2][arow] = av.z;
        As[acol + 3][arow] = av.w;
        if (NT) {
            float4 bv = *(const float4*)(Bb + (size_t)arow * ldb + k0 + acol);
            Bs[acol + 0][arow] = bv.x;
            Bs[acol + 1][arow] = bv.y;
            Bs[acol + 2][arow] = bv.z;
            Bs[acol + 3][arow] = bv.w;
        } else {
            float4 bv = *(const float4*)(Bb + (size_t)(k0 + brow) * ldb + bcol);
            *(float4*)&Bs[brow][bcol] = bv;
        }
        __syncthreads();

#pragma unroll
        for (int kk = 0; kk < BK; ++kk) {
            float a[TM], b[TN];
            *(float4*)&a[0] = *(const float4*)&As[kk][ty * TM];
            *(float4*)&a[4] = *(const float4*)&As[kk][ty * TM + 4];
            *(float4*)&b[0] = *(const float4*)&Bs[kk][tx * TN];
            *(float4*)&b[4] = *(const float4*)&Bs[kk][tx * TN + 4];
#pragma unroll
            for (int i = 0; i < TM; ++i)
#pragma unroll
                for (int j = 0; j < TN; ++j)
                    acc[i][j] = fmaf(a[i], b[j], acc[i][j]);
        }
        __syncthreads();
    }

    const int crow = blockIdx.y * BM + ty * TM;
    const int ccol = blockIdx.x * BN + tx * TN;
    float bb[TN];
#pragma unroll
    for (int j = 0; j < TN; ++j) bb[j] = bias ? bias[ccol + j] : 0.0f;

#pragma unroll
    for (int i = 0; i < TM; ++i) {
        float4 o0, o1;
        o0.x = acc[i][0] * alpha + bb[0];
        o0.y = acc[i][1] * alpha + bb[1];
        o0.z = acc[i][2] * alpha + bb[2];
        o0.w = acc[i][3] * alpha + bb[3];
        o1.x = acc[i][4] * alpha + bb[4];
        o1.y = acc[i][5] * alpha + bb[5];
        o1.z = acc[i][6] * alpha + bb[6];
        o1.w = acc[i][7] * alpha + bb[7];
        *(float4*)&C[(size_t)(crow + i) * ldc + ccol]     = o0;
        *(float4*)&C[(size_t)(crow + i) * ldc + ccol + 4] = o1;
    }
}

// ---------------- Kernels ------------------------------------------------

// Projection: C = A @ W^T + b.  asel: 0 -> A from arg, 1 -> A = g_ao.
// csel: 0/1/2 -> g_Q/g_K/g_V, 3 -> Cext (d_out).
__global__ void __launch_bounds__(256) proj_kernel(
    const float* __restrict__ Aext, const float* __restrict__ W,
    const float* __restrict__ bias, float* Cext, int asel, int csel)
{
    const float* A = asel ? g_ao : Aext;
    float* C = (csel == 0) ? g_Q : (csel == 1) ? g_K : (csel == 2) ? g_V : Cext;
    gemm_body<true>(A, U, W, U, C, U, U, 1.0f, bias);
}

// scores[b,h,t,s] = (1/16) * sum_d Q[row(b,h/4,t), (h%4)*256+d] * K[row(b,h/4,s), (h%4)*256+d]
__global__ void __launch_bounds__(256) scores_kernel()
{
    const int z = blockIdx.z, b = z >> 3, h = z & 7;
    const size_t off = ((size_t)(b * NCHAN + (h >> 2)) * TLEN) * U + (size_t)(h & 3) * 256;
    gemm_body<true>(g_Q + off, U, g_K + off, U,
                    g_att + (size_t)z * TLEN * TLEN, TLEN,
                    256, 0.0625f, nullptr);
}

// Row softmax over the last dim of g_att (32768 rows of 1024)
__global__ void __launch_bounds__(256) softmax_kernel()
{
    const size_t row = blockIdx.x;
    float4* p = (float4*)(g_att + row * TLEN);
    const int tid = threadIdx.x;

    float4 x = p[tid];
    float m = fmaxf(fmaxf(x.x, x.y), fmaxf(x.z, x.w));
#pragma unroll
    for (int o = 16; o; o >>= 1) m = fmaxf(m, __shfl_xor_sync(0xffffffffu, m, o));

    __shared__ float rmax[8];
    __shared__ float rsum[8];
    if ((tid & 31) == 0) rmax[tid >> 5] = m;
    __syncthreads();
    float bm = fmaxf(fmaxf(fmaxf(rmax[0], rmax[1]), fmaxf(rmax[2], rmax[3])),
                     fmaxf(fmaxf(rmax[4], rmax[5]), fmaxf(rmax[6], rmax[7])));

    float e0 = __expf(x.x - bm), e1 = __expf(x.y - bm);
    float e2 = __expf(x.z - bm), e3 = __expf(x.w - bm);
    float s = e0 + e1 + e2 + e3;
#pragma unroll
    for (int o = 16; o; o >>= 1) s += __shfl_xor_sync(0xffffffffu, s, o);
    if ((tid & 31) == 0) rsum[tid >> 5] = s;
    __syncthreads();
    float tot = rsum[0] + rsum[1] + rsum[2] + rsum[3]
              + rsum[4] + rsum[5] + rsum[6] + rsum[7];
    float inv = 1.0f / tot;

    p[tid] = make_float4(e0 * inv, e1 * inv, e2 * inv, e3 * inv);
}

// out[b,n,t,h*128+dv] = sum_s att[(b,h)][t][s] * V[row(b,n,s), h*128+dv]
__global__ void __launch_bounds__(256) attv_kernel()
{
    const int z = blockIdx.z;
    const int b = z >> 4, h = (z >> 1) & 7, n = z & 1;
    const float* A = g_att + (size_t)(b * HEADS + h) * TLEN * TLEN;
    const size_t voff = ((size_t)(b * NCHAN + n) * TLEN) * U + (size_t)h * DK;
    gemm_body<false>(A, TLEN, g_V + voff, U, g_ao + voff, U,
                     TLEN, 1.0f, nullptr);
}

// ---------------- Launch --------------------------------------------------

extern "C" void kernel_launch(void* const* d_in, const int* in_sizes, int n_in,
                              void* d_out, int out_size)
{
    const float* x  = (const float*)d_in[0];
    // d_in[1] = batch_size (int scalar) — shapes are compile-time constants
    const float* Wq = (const float*)d_in[2];
    const float* bq = (const float*)d_in[3];
    const float* Wk = (const float*)d_in[4];
    const float* bk = (const float*)d_in[5];
    const float* Wv = (const float*)d_in[6];
    const float* bv = (const float*)d_in[7];
    const float* Wo = (const float*)d_in[8];
    const float* bo = (const float*)d_in[9];
    float* out = (float*)d_out;

    dim3 blk(256);
    dim3 gproj(U / BN, MROWS / BM);           // (8, 64)

    proj_kernel<<<gproj, blk>>>(x, Wq, bq, nullptr, 0, 0);
    proj_kernel<<<gproj, blk>>>(x, Wk, bk, nullptr, 0, 1);
    proj_kernel<<<gproj, blk>>>(x, Wv, bv, nullptr, 0, 2);

    scores_kernel<<<dim3(TLEN / BN, TLEN / BM, BATCH * HEADS), blk>>>();

    softmax_kernel<<<BATCH * HEADS * TLEN, blk>>>();

    attv_kernel<<<dim3(1, TLEN / BM, BATCH * HEADS * NCHAN), blk>>>();

    proj_kernel<<<gproj, blk>>>(nullptr, Wo, bo, out, 1, 3);
}

// round 4
// speedup vs baseline: 2.5529x; 2.5529x over previous
#include <cuda_runtime.h>
#include <cuda_bf16.h>
#include <cstdint>

// ---------------- Problem constants ----------------
#define U      1024
#define BATCH  4
#define NCHAN  2
#define TLEN   1024
#define HEADS  8
#define DK     128
#define MROWS  (BATCH * NCHAN * TLEN)          // 8192
#define MS     ((size_t)MROWS * U)             // 8M elements
#define ATTN_E ((size_t)BATCH * HEADS * TLEN * TLEN)  // 32M elements

// ---------------- Scratch (device globals; allocation-free) ----------------
__device__ __nv_bfloat16 g_xh[MS],  g_xl[MS];
__device__ __nv_bfloat16 g_Wqh[U*U], g_Wql[U*U];
__device__ __nv_bfloat16 g_Wkh[U*U], g_Wkl[U*U];
__device__ __nv_bfloat16 g_Wvh[U*U], g_Wvl[U*U];
__device__ __nv_bfloat16 g_Woh[U*U], g_Wol[U*U];
__device__ __nv_bfloat16 g_Qh[MS],  g_Ql[MS];
__device__ __nv_bfloat16 g_Kh[MS],  g_Kl[MS];
__device__ float         g_V[MS];
__device__ __nv_bfloat16 g_Vth[MS], g_Vtl[MS];
__device__ float         g_att[ATTN_E];
__device__ __nv_bfloat16 g_atth[ATTN_E], g_attl[ATTN_E];
__device__ __nv_bfloat16 g_aoh[MS], g_aol[MS];

// ---------------- Helpers ----------------
__device__ __forceinline__ uint32_t smem_u32(const void* p) {
    uint32_t a;
    asm("{ .reg .u64 t; cvta.to.shared.u64 t, %1; cvt.u32.u64 %0, t; }" : "=r"(a) : "l"(p));
    return a;
}
__device__ __forceinline__ void cp16(uint32_t dst, const void* src) {
    asm volatile("cp.async.cg.shared.global [%0], [%1], 16;" :: "r"(dst), "l"(src));
}
#define CP_COMMIT asm volatile("cp.async.commit_group;" ::: "memory")
#define CP_WAIT(n) asm volatile("cp.async.wait_group %0;" :: "n"(n) : "memory")

__device__ __forceinline__ void ldsm4(uint32_t (&r)[4], uint32_t addr) {
    asm volatile("ldmatrix.sync.aligned.m8n8.x4.shared.b16 {%0,%1,%2,%3}, [%4];"
        : "=r"(r[0]), "=r"(r[1]), "=r"(r[2]), "=r"(r[3]) : "r"(addr));
}
__device__ __forceinline__ void mma16816(float (&c)[4], const uint32_t (&a)[4],
                                         uint32_t b0, uint32_t b1) {
    asm volatile(
        "mma.sync.aligned.m16n8k16.row.col.f32.bf16.bf16.f32 "
        "{%0,%1,%2,%3}, {%4,%5,%6,%7}, {%8,%9}, {%0,%1,%2,%3};"
        : "+f"(c[0]), "+f"(c[1]), "+f"(c[2]), "+f"(c[3])
        : "r"(a[0]), "r"(a[1]), "r"(a[2]), "r"(a[3]), "r"(b0), "r"(b1));
}
__device__ __forceinline__ void split1(float v, __nv_bfloat16& h, __nv_bfloat16& l) {
    h = __float2bfloat16(v);
    l = __float2bfloat16(v - __bfloat162float(h));
}

// ---------------- bf16x3 GEMM core (mma.sync) ----------------
// C[128,128] = alpha*(A@B^T) + bias.  A,B hi/lo bf16, K-major. 256 threads.
// Tile smem: 128 rows x 32 bf16 cols, row stride 80B (16B pad) -> 10240B/tile.
#define TILE_B   10240
#define SM_AH    0
#define SM_AL    10240
#define SM_BH    20480
#define SM_BL    30720
#define SMEM_STAGE 40960
#define SMEM_BYTES (2 * SMEM_STAGE)

__device__ __forceinline__ void stage_tile(uint32_t sdst, const __nv_bfloat16* __restrict__ g,
                                           int ld, int tid) {
#pragma unroll
    for (int p = 0; p < 2; ++p) {
        int idx = p * 256 + tid;        // 512 chunks of 16B
        int row = idx >> 2, c = idx & 3;
        cp16(sdst + row * 80 + c * 16, g + (size_t)row * ld + c * 8);
    }
}

__device__ __forceinline__ void gemm_core(
    const __nv_bfloat16* __restrict__ Ah, const __nv_bfloat16* __restrict__ Al, int lda,
    const __nv_bfloat16* __restrict__ Bh, const __nv_bfloat16* __restrict__ Bl, int ldb,
    int K, float alpha, const float* __restrict__ bias,
    float* Cf, __nv_bfloat16* Ch, __nv_bfloat16* Cl, int ldc, int mode)
{
    extern __shared__ char smem[];
    const uint32_t sb = smem_u32(smem);
    const int tid = threadIdx.x;
    const int l   = tid & 31;
    const int wid = tid >> 5;
    const int wm  = wid >> 1;      // 0..3 -> M
    const int wn  = wid & 1;       // 0..1 -> N

    // ldmatrix lane offsets (within a tile): row = base + (l&15); +16B for lanes>=16
    const uint32_t lrow = (uint32_t)(l & 15) * 80 + (uint32_t)(l >> 4) * 16;
    const uint32_t aoff = (uint32_t)(wm * 32) * 80 + lrow;
    const uint32_t boff = (uint32_t)(wn * 64) * 80 + lrow;

    float acc[2][8][4];
#pragma unroll
    for (int i = 0; i < 2; ++i)
#pragma unroll
        for (int j = 0; j < 8; ++j)
#pragma unroll
            for (int q = 0; q < 4; ++q) acc[i][j][q] = 0.0f;

    const int nst = K >> 5;  // BK=32 chunks

    // prefetch stage 0
    stage_tile(sb + SM_AH, Ah, lda, tid);
    stage_tile(sb + SM_AL, Al, lda, tid);
    stage_tile(sb + SM_BH, Bh, ldb, tid);
    stage_tile(sb + SM_BL, Bl, ldb, tid);
    CP_COMMIT;

    for (int st = 0; st < nst; ++st) {
        if (st + 1 < nst) {
            const uint32_t so = ((st + 1) & 1) * SMEM_STAGE;
            const int k0 = (st + 1) << 5;
            stage_tile(sb + so + SM_AH, Ah + k0, lda, tid);
            stage_tile(sb + so + SM_AL, Al + k0, lda, tid);
            stage_tile(sb + so + SM_BH, Bh + k0, ldb, tid);
            stage_tile(sb + so + SM_BL, Bl + k0, ldb, tid);
            CP_COMMIT;
            CP_WAIT(1);
        } else {
            CP_WAIT(0);
        }
        __syncthreads();

        const uint32_t so = (st & 1) * SMEM_STAGE;
#pragma unroll
        for (int k16 = 0; k16 < 2; ++k16) {
            const uint32_t kb = (uint32_t)k16 * 32;
            uint32_t ah[2][4], al[2][4], bh[4][4], bl[4][4];
#pragma unroll
            for (int i = 0; i < 2; ++i) {
                ldsm4(ah[i], sb + so + SM_AH + aoff + i * (16 * 80) + kb);
                ldsm4(al[i], sb + so + SM_AL + aoff + i * (16 * 80) + kb);
            }
#pragma unroll
            for (int j2 = 0; j2 < 4; ++j2) {
                ldsm4(bh[j2], sb + so + SM_BH + boff + j2 * (16 * 80) + kb);
                ldsm4(bl[j2], sb + so + SM_BL + boff + j2 * (16 * 80) + kb);
            }
#pragma unroll
            for (int j2 = 0; j2 < 4; ++j2) {
#pragma unroll
                for (int jj = 0; jj < 2; ++jj) {
                    const int j = j2 * 2 + jj;
                    const uint32_t bh0 = bh[j2][jj], bh1 = bh[j2][jj + 2];
                    const uint32_t bl0 = bl[j2][jj], bl1 = bl[j2][jj + 2];
#pragma unroll
                    for (int i = 0; i < 2; ++i) {
                        mma16816(acc[i][j], ah[i], bh0, bh1);
                        mma16816(acc[i][j], al[i], bh0, bh1);
                        mma16816(acc[i][j], ah[i], bl0, bl1);
                    }
                }
            }
        }
        __syncthreads();
    }

    // ---- Epilogue ----
    const int rbase = wm * 32 + (l >> 2);
    const int cbase = wn * 64 + 2 * (l & 3);
#pragma unroll
    for (int i = 0; i < 2; ++i) {
#pragma unroll
        for (int j = 0; j < 8; ++j) {
            const int row = rbase + i * 16;
            const int col = cbase + j * 8;
            float b0 = 0.0f, b1 = 0.0f;
            if (bias) { b0 = bias[col]; b1 = bias[col + 1]; }
            float v0 = acc[i][j][0] * alpha + b0;
            float v1 = acc[i][j][1] * alpha + b1;
            float v2 = acc[i][j][2] * alpha + b0;
            float v3 = acc[i][j][3] * alpha + b1;
            if (mode == 0) {
                *(float2*)(Cf + (size_t)row * ldc + col)       = make_float2(v0, v1);
                *(float2*)(Cf + (size_t)(row + 8) * ldc + col) = make_float2(v2, v3);
            } else {
                __nv_bfloat16 h0, l0, h1, l1;
                split1(v0, h0, l0); split1(v1, h1, l1);
                *(__nv_bfloat162*)(Ch + (size_t)row * ldc + col) = __nv_bfloat162(h0, h1);
                *(__nv_bfloat162*)(Cl + (size_t)row * ldc + col) = __nv_bfloat162(l0, l1);
                split1(v2, h0, l0); split1(v3, h1, l1);
                *(__nv_bfloat162*)(Ch + (size_t)(row + 8) * ldc + col) = __nv_bfloat162(h0, h1);
                *(__nv_bfloat162*)(Cl + (size_t)(row + 8) * ldc + col) = __nv_bfloat162(l0, l1);
            }
        }
    }
}

// ---------------- GEMM wrappers ----------------
__global__ void __launch_bounds__(256) k_proj(const float* __restrict__ bias,
                                              float* cout, int which)
{
    const size_t m0 = (size_t)blockIdx.y * 128, n0 = (size_t)blockIdx.x * 128;
    const __nv_bfloat16 *Ah, *Al, *Bh, *Bl;
    float* Cf = nullptr; __nv_bfloat16 *Ch = nullptr, *Cl = nullptr;
    int mode;
    switch (which) {
        case 0: Ah = g_xh;  Al = g_xl;  Bh = g_Wqh; Bl = g_Wql;
                Ch = g_Qh;  Cl = g_Ql;  mode = 1; break;
        case 1: Ah = g_xh;  Al = g_xl;  Bh = g_Wkh; Bl = g_Wkl;
                Ch = g_Kh;  Cl = g_Kl;  mode = 1; break;
        case 2: Ah = g_xh;  Al = g_xl;  Bh = g_Wvh; Bl = g_Wvl;
                Cf = g_V;   mode = 0; break;
        default: Ah = g_aoh; Al = g_aol; Bh = g_Woh; Bl = g_Wol;
                Cf = cout;  mode = 0; break;
    }
    const size_t co = m0 * U + n0;
    gemm_core(Ah + m0 * U, Al + m0 * U, U,
              Bh + n0 * U, Bl + n0 * U, U,
              U, 1.0f, bias + n0,
              Cf ? Cf + co : nullptr,
              Ch ? Ch + co : nullptr,
              Cl ? Cl + co : nullptr, U, mode);
}

__global__ void __launch_bounds__(256) k_scores()
{
    const int z = blockIdx.z, b = z >> 3, h = z & 7;
    const size_t m0 = (size_t)blockIdx.y * 128, n0 = (size_t)blockIdx.x * 128;
    const size_t off = ((size_t)(b * NCHAN + (h >> 2)) * TLEN) * U + (size_t)(h & 3) * 256;
    float* C = g_att + (size_t)z * TLEN * TLEN + m0 * TLEN + n0;
    gemm_core(g_Qh + off + m0 * U, g_Ql + off + m0 * U, U,
              g_Kh + off + n0 * U, g_Kl + off + n0 * U, U,
              256, 0.0625f, nullptr, C, nullptr, nullptr, TLEN, 0);
}

__global__ void __launch_bounds__(256) k_attv()
{
    const int z = blockIdx.z;
    const int b = z >> 4, h = (z >> 1) & 7, n = z & 1;
    const size_t m0 = (size_t)blockIdx.y * 128;
    const size_t aoff = (size_t)(b * HEADS + h) * TLEN * TLEN + m0 * TLEN;
    const size_t boff = (size_t)(b * NCHAN + n) * TLEN * U + (size_t)h * DK * TLEN;
    const size_t coff = ((size_t)(b * NCHAN + n) * TLEN + m0) * U + (size_t)h * DK;
    gemm_core(g_atth + aoff, g_attl + aoff, TLEN,
              g_Vth + boff,  g_Vtl + boff,  TLEN,
              TLEN, 1.0f, nullptr, nullptr,
              g_aoh + coff, g_aol + coff, U, 1);
}

// ---------------- Conversion / softmax kernels ----------------
__global__ void __launch_bounds__(256) split_kernel(const float* __restrict__ src, int sel)
{
    __nv_bfloat16 *h, *l;
    switch (sel) {
        case 0: h = g_xh;  l = g_xl;  break;
        case 1: h = g_Wqh; l = g_Wql; break;
        case 2: h = g_Wkh; l = g_Wkl; break;
        case 3: h = g_Wvh; l = g_Wvl; break;
        default: h = g_Woh; l = g_Wol; break;
    }
    const size_t i = (size_t)blockIdx.x * 256 + threadIdx.x;
    float4 v = ((const float4*)src)[i];
    __nv_bfloat16 h0, l0, h1, l1, h2, l2, h3, l3;
    split1(v.x, h0, l0); split1(v.y, h1, l1);
    split1(v.z, h2, l2); split1(v.w, h3, l3);
    ((__nv_bfloat162*)(h + i * 4))[0] = __nv_bfloat162(h0, h1);
    ((__nv_bfloat162*)(h + i * 4))[1] = __nv_bfloat162(h2, h3);
    ((__nv_bfloat162*)(l + i * 4))[0] = __nv_bfloat162(l0, l1);
    ((__nv_bfloat162*)(l + i * 4))[1] = __nv_bfloat162(l2, l3);
}

// Transpose + split V per (b,n): Vt[d][s] = V[s][d]
__global__ void vtrans_kernel()
{
    __shared__ float tile[32][33];
    const int z = blockIdx.z;
    const int d0 = blockIdx.x * 32, s0 = blockIdx.y * 32;
    const float* src = g_V + (size_t)z * TLEN * U;
    tile[threadIdx.y][threadIdx.x] = src[(size_t)(s0 + threadIdx.y) * U + d0 + threadIdx.x];
    __syncthreads();
    float v = tile[threadIdx.x][threadIdx.y];       // = V[s0+tx][d0+ty]
    const size_t o = (size_t)z * TLEN * U + (size_t)(d0 + threadIdx.y) * TLEN + s0 + threadIdx.x;
    __nv_bfloat16 hh, ll;
    split1(v, hh, ll);
    g_Vth[o] = hh; g_Vtl[o] = ll;
}

__global__ void __launch_bounds__(256) softmax_kernel()
{
    const size_t row = blockIdx.x;
    const float4* p = (const float4*)(g_att + row * TLEN);
    const int tid = threadIdx.x;

    float4 x = p[tid];
    float m = fmaxf(fmaxf(x.x, x.y), fmaxf(x.z, x.w));
#pragma unroll
    for (int o = 16; o; o >>= 1) m = fmaxf(m, __shfl_xor_sync(0xffffffffu, m, o));
    __shared__ float rmax[8], rsum[8];
    if ((tid & 31) == 0) rmax[tid >> 5] = m;
    __syncthreads();
    float bm = fmaxf(fmaxf(fmaxf(rmax[0], rmax[1]), fmaxf(rmax[2], rmax[3])),
                     fmaxf(fmaxf(rmax[4], rmax[5]), fmaxf(rmax[6], rmax[7])));
    float e0 = __expf(x.x - bm), e1 = __expf(x.y - bm);
    float e2 = __expf(x.z - bm), e3 = __expf(x.w - bm);
    float s = e0 + e1 + e2 + e3;
#pragma unroll
    for (int o = 16; o; o >>= 1) s += __shfl_xor_sync(0xffffffffu, s, o);
    if ((tid & 31) == 0) rsum[tid >> 5] = s;
    __syncthreads();
    float inv = 1.0f / (rsum[0] + rsum[1] + rsum[2] + rsum[3]
                      + rsum[4] + rsum[5] + rsum[6] + rsum[7]);

    const size_t base = row * TLEN + (size_t)tid * 4;
    __nv_bfloat16 h0, l0, h1, l1, h2, l2, h3, l3;
    split1(e0 * inv, h0, l0); split1(e1 * inv, h1, l1);
    split1(e2 * inv, h2, l2); split1(e3 * inv, h3, l3);
    ((__nv_bfloat162*)(g_atth + base))[0] = __nv_bfloat162(h0, h1);
    ((__nv_bfloat162*)(g_atth + base))[1] = __nv_bfloat162(h2, h3);
    ((__nv_bfloat162*)(g_attl + base))[0] = __nv_bfloat162(l0, l1);
    ((__nv_bfloat162*)(g_attl + base))[1] = __nv_bfloat162(l2, l3);
}

// ---------------- Launch ----------------
extern "C" void kernel_launch(void* const* d_in, const int* in_sizes, int n_in,
                              void* d_out, int out_size)
{
    const float* x  = (const float*)d_in[0];
    const float* Wq = (const float*)d_in[2];
    const float* bq = (const float*)d_in[3];
    const float* Wk = (const float*)d_in[4];
    const float* bk = (const float*)d_in[5];
    const float* Wv = (const float*)d_in[6];
    const float* bv = (const float*)d_in[7];
    const float* Wo = (const float*)d_in[8];
    const float* bo = (const float*)d_in[9];
    float* out = (float*)d_out;

    cudaFuncSetAttribute(k_proj,   cudaFuncAttributeMaxDynamicSharedMemorySize, SMEM_BYTES);
    cudaFuncSetAttribute(k_scores, cudaFuncAttributeMaxDynamicSharedMemorySize, SMEM_BYTES);
    cudaFuncSetAttribute(k_attv,   cudaFuncAttributeMaxDynamicSharedMemorySize, SMEM_BYTES);

    split_kernel<<<MS / 1024, 256>>>(x, 0);
    split_kernel<<<(U * U) / 1024, 256>>>(Wq, 1);
    split_kernel<<<(U * U) / 1024, 256>>>(Wk, 2);
    split_kernel<<<(U * U) / 1024, 256>>>(Wv, 3);
    split_kernel<<<(U * U) / 1024, 256>>>(Wo, 4);

    dim3 gproj(U / 128, MROWS / 128);   // (8, 64)
    k_proj<<<gproj, 256, SMEM_BYTES>>>(bq, nullptr, 0);
    k_proj<<<gproj, 256, SMEM_BYTES>>>(bk, nullptr, 1);
    k_proj<<<gproj, 256, SMEM_BYTES>>>(bv, nullptr, 2);

    vtrans_kernel<<<dim3(32, 32, BATCH * NCHAN), dim3(32, 32)>>>();

    k_scores<<<dim3(8, 8, BATCH * HEADS), 256, SMEM_BYTES>>>();

    softmax_kernel<<<BATCH * HEADS * TLEN, 256>>>();

    k_attv<<<dim3(1, 8, BATCH * HEADS * NCHAN), 256, SMEM_BYTES>>>();

    k_proj<<<gproj, 256, SMEM_BYTES>>>(bo, out, 3);
}

// round 5
// speedup vs baseline: 2.7040x; 1.0592x over previous
#include <cuda_runtime.h>
#include <cuda_bf16.h>
#include <cstdint>

// ---------------- Problem constants ----------------
#define U      1024
#define BATCH  4
#define NCHAN  2
#define TLEN   1024
#define HEADS  8
#define DK     128
#define MROWS  (BATCH * NCHAN * TLEN)          // 8192
#define MS     ((size_t)MROWS * U)             // 8M elements
#define ATTN_E ((size_t)BATCH * HEADS * TLEN * TLEN)  // 32M elements

// ---------------- Scratch (device globals; allocation-free) ----------------
__device__ __nv_bfloat16 g_xh[MS],  g_xl[MS];
__device__ __nv_bfloat16 g_Wqh[U*U], g_Wql[U*U];
__device__ __nv_bfloat16 g_Wkh[U*U], g_Wkl[U*U];
__device__ __nv_bfloat16 g_Wvh[U*U], g_Wvl[U*U];
__device__ __nv_bfloat16 g_Woh[U*U], g_Wol[U*U];
__device__ __nv_bfloat16 g_Qh[MS],  g_Ql[MS];
__device__ __nv_bfloat16 g_Kh[MS],  g_Kl[MS];
__device__ float         g_V[MS];
__device__ __nv_bfloat16 g_Vth[MS], g_Vtl[MS];
__device__ float         g_att[ATTN_E];
__device__ __nv_bfloat16 g_atth[ATTN_E], g_attl[ATTN_E];
__device__ __nv_bfloat16 g_aoh[MS], g_aol[MS];

// ---------------- Helpers ----------------
__device__ __forceinline__ uint32_t smem_u32(const void* p) {
    uint32_t a;
    asm("{ .reg .u64 t; cvta.to.shared.u64 t, %1; cvt.u32.u64 %0, t; }" : "=r"(a) : "l"(p));
    return a;
}
__device__ __forceinline__ void cp16(uint32_t dst, const void* src) {
    asm volatile("cp.async.cg.shared.global [%0], [%1], 16;" :: "r"(dst), "l"(src));
}
#define CP_COMMIT asm volatile("cp.async.commit_group;" ::: "memory")
#define CP_WAIT(n) asm volatile("cp.async.wait_group %0;" :: "n"(n) : "memory")

__device__ __forceinline__ void ldsm4(uint32_t (&r)[4], uint32_t addr) {
    asm volatile("ldmatrix.sync.aligned.m8n8.x4.shared.b16 {%0,%1,%2,%3}, [%4];"
        : "=r"(r[0]), "=r"(r[1]), "=r"(r[2]), "=r"(r[3]) : "r"(addr));
}
__device__ __forceinline__ void mma16816(float (&c)[4], const uint32_t (&a)[4],
                                         uint32_t b0, uint32_t b1) {
    asm volatile(
        "mma.sync.aligned.m16n8k16.row.col.f32.bf16.bf16.f32 "
        "{%0,%1,%2,%3}, {%4,%5,%6,%7}, {%8,%9}, {%0,%1,%2,%3};"
        : "+f"(c[0]), "+f"(c[1]), "+f"(c[2]), "+f"(c[3])
        : "r"(a[0]), "r"(a[1]), "r"(a[2]), "r"(a[3]), "r"(b0), "r"(b1));
}
__device__ __forceinline__ void split1(float v, __nv_bfloat16& h, __nv_bfloat16& l) {
    h = __float2bfloat16(v);
    l = __float2bfloat16(v - __bfloat162float(h));
}

// ---------------- bf16x3 GEMM core (mma.sync) ----------------
// C[128,128] = alpha*(A@B^T) + bias.  A,B hi/lo bf16, K-major. 256 threads.
// Tile smem: 128 rows x 32 bf16 cols, row stride 80B (16B pad) -> 10240B/tile.
#define SM_AH    0
#define SM_AL    10240
#define SM_BH    20480
#define SM_BL    30720
#define SMEM_STAGE 40960
#define SMEM_BYTES (2 * SMEM_STAGE)

__device__ __forceinline__ void stage_tile(uint32_t sdst, const __nv_bfloat16* __restrict__ g,
                                           int ld, int tid) {
#pragma unroll
    for (int p = 0; p < 2; ++p) {
        int idx = p * 256 + tid;        // 512 chunks of 16B
        int row = idx >> 2, c = idx & 3;
        cp16(sdst + row * 80 + c * 16, g + (size_t)row * ld + c * 8);
    }
}
__device__ __forceinline__ void stage_all(uint32_t sb,
    const __nv_bfloat16* Ah, const __nv_bfloat16* Al, int lda,
    const __nv_bfloat16* Bh, const __nv_bfloat16* Bl, int ldb, int tid) {
    stage_tile(sb + SM_AH, Ah, lda, tid);
    stage_tile(sb + SM_AL, Al, lda, tid);
    stage_tile(sb + SM_BH, Bh, ldb, tid);
    stage_tile(sb + SM_BL, Bl, ldb, tid);
}

// MODE 0: fp32 out (Cf). MODE 1: hi/lo bf16 out (Ch/Cl).
template <int NST, int MODE, bool HAS_BIAS>
__device__ __forceinline__ void gemm_core(
    const __nv_bfloat16* __restrict__ Ah, const __nv_bfloat16* __restrict__ Al, int lda,
    const __nv_bfloat16* __restrict__ Bh, const __nv_bfloat16* __restrict__ Bl, int ldb,
    float alpha, const float* __restrict__ bias,
    float* Cf, __nv_bfloat16* Ch, __nv_bfloat16* Cl, int ldc)
{
    extern __shared__ char smem[];
    const uint32_t sb = smem_u32(smem);
    const int tid = threadIdx.x;
    const int l   = tid & 31;
    const int wid = tid >> 5;
    const int wm  = wid >> 1;      // 0..3 -> M
    const int wn  = wid & 1;       // 0..1 -> N

    const uint32_t lrow = (uint32_t)(l & 15) * 80 + (uint32_t)(l >> 4) * 16;
    const uint32_t aoff = (uint32_t)(wm * 32) * 80 + lrow;
    const uint32_t boff = (uint32_t)(wn * 64) * 80 + lrow;

    float acc[2][8][4];
#pragma unroll
    for (int i = 0; i < 2; ++i)
#pragma unroll
        for (int j = 0; j < 8; ++j)
#pragma unroll
            for (int q = 0; q < 4; ++q) acc[i][j][q] = 0.0f;

    // prologue: stage 0
    stage_all(sb, Ah, Al, lda, Bh, Bl, ldb, tid);
    CP_COMMIT;

    for (int st = 0; st < NST; ++st) {
        CP_WAIT(0);            // stage st landed (st+1 not yet issued)
        __syncthreads();       // data visible to all; prior-stage readers done

        if (st + 1 < NST) {    // overlap next-stage copies with this stage's MMAs
            const uint32_t so2 = (uint32_t)((st + 1) & 1) * SMEM_STAGE;
            const int k0 = (st + 1) << 5;
            stage_all(sb + so2, Ah + k0, Al + k0, lda, Bh + k0, Bl + k0, ldb, tid);
            CP_COMMIT;
        }

        const uint32_t so = (uint32_t)(st & 1) * SMEM_STAGE;
#pragma unroll
        for (int k16 = 0; k16 < 2; ++k16) {
            const uint32_t kb = (uint32_t)k16 * 32;
            uint32_t ah[2][4], al[2][4], bh[4][4], bl[4][4];
#pragma unroll
            for (int i = 0; i < 2; ++i) {
                ldsm4(ah[i], sb + so + SM_AH + aoff + i * (16 * 80) + kb);
                ldsm4(al[i], sb + so + SM_AL + aoff + i * (16 * 80) + kb);
            }
#pragma unroll
            for (int j2 = 0; j2 < 4; ++j2) {
                ldsm4(bh[j2], sb + so + SM_BH + boff + j2 * (16 * 80) + kb);
                ldsm4(bl[j2], sb + so + SM_BL + boff + j2 * (16 * 80) + kb);
            }
#pragma unroll
            for (int j2 = 0; j2 < 4; ++j2) {
#pragma unroll
                for (int jj = 0; jj < 2; ++jj) {
                    const int j = j2 * 2 + jj;
                    const uint32_t bh0 = bh[j2][jj], bh1 = bh[j2][jj + 2];
                    const uint32_t bl0 = bl[j2][jj], bl1 = bl[j2][jj + 2];
#pragma unroll
                    for (int i = 0; i < 2; ++i) {
                        mma16816(acc[i][j], ah[i], bh0, bh1);
                        mma16816(acc[i][j], al[i], bh0, bh1);
                        mma16816(acc[i][j], ah[i], bl0, bl1);
                    }
                }
            }
        }
        __syncthreads();
    }

    // ---- Epilogue ----
    const int rbase = wm * 32 + (l >> 2);
    const int cbase = wn * 64 + 2 * (l & 3);
#pragma unroll
    for (int i = 0; i < 2; ++i) {
#pragma unroll
        for (int j = 0; j < 8; ++j) {
            const int row = rbase + i * 16;
            const int col = cbase + j * 8;
            float b0 = 0.0f, b1 = 0.0f;
            if (HAS_BIAS) { b0 = bias[col]; b1 = bias[col + 1]; }
            float v0 = acc[i][j][0] * alpha + b0;
            float v1 = acc[i][j][1] * alpha + b1;
            float v2 = acc[i][j][2] * alpha + b0;
            float v3 = acc[i][j][3] * alpha + b1;
            if (MODE == 0) {
                *(float2*)(Cf + (size_t)row * ldc + col)       = make_float2(v0, v1);
                *(float2*)(Cf + (size_t)(row + 8) * ldc + col) = make_float2(v2, v3);
            } else {
                __nv_bfloat16 h0, l0, h1, l1;
                split1(v0, h0, l0); split1(v1, h1, l1);
                *(__nv_bfloat162*)(Ch + (size_t)row * ldc + col) = __nv_bfloat162(h0, h1);
                *(__nv_bfloat162*)(Cl + (size_t)row * ldc + col) = __nv_bfloat162(l0, l1);
                split1(v2, h0, l0); split1(v3, h1, l1);
                *(__nv_bfloat162*)(Ch + (size_t)(row + 8) * ldc + col) = __nv_bfloat162(h0, h1);
                *(__nv_bfloat162*)(Cl + (size_t)(row + 8) * ldc + col) = __nv_bfloat162(l0, l1);
            }
        }
    }
}

// ---------------- GEMM wrappers ----------------
// Merged Q/K/V projections: z selects the weight/output set (one launch, one tail)
__global__ void __launch_bounds__(256) k_qkv(const float* __restrict__ bq,
                                             const float* __restrict__ bk,
                                             const float* __restrict__ bv)
{
    const size_t m0 = (size_t)blockIdx.y * 128, n0 = (size_t)blockIdx.x * 128;
    const size_t co = m0 * U + n0;
    const int z = blockIdx.z;
    if (z == 0) {
        gemm_core<32, 1, true>(g_xh + m0 * U, g_xl + m0 * U, U,
                               g_Wqh + n0 * U, g_Wql + n0 * U, U,
                               1.0f, bq + n0, nullptr, g_Qh + co, g_Ql + co, U);
    } else if (z == 1) {
        gemm_core<32, 1, true>(g_xh + m0 * U, g_xl + m0 * U, U,
                               g_Wkh + n0 * U, g_Wkl + n0 * U, U,
                               1.0f, bk + n0, nullptr, g_Kh + co, g_Kl + co, U);
    } else {
        gemm_core<32, 0, true>(g_xh + m0 * U, g_xl + m0 * U, U,
                               g_Wvh + n0 * U, g_Wvl + n0 * U, U,
                               1.0f, bv + n0, g_V + co, nullptr, nullptr, U);
    }
}

__global__ void __launch_bounds__(256) k_out(const float* __restrict__ bo, float* out)
{
    const size_t m0 = (size_t)blockIdx.y * 128, n0 = (size_t)blockIdx.x * 128;
    gemm_core<32, 0, true>(g_aoh + m0 * U, g_aol + m0 * U, U,
                           g_Woh + n0 * U, g_Wol + n0 * U, U,
                           1.0f, bo + n0, out + m0 * U + n0, nullptr, nullptr, U);
}

__global__ void __launch_bounds__(256) k_scores()
{
    const int z = blockIdx.z, b = z >> 3, h = z & 7;
    const size_t m0 = (size_t)blockIdx.y * 128, n0 = (size_t)blockIdx.x * 128;
    const size_t off = ((size_t)(b * NCHAN + (h >> 2)) * TLEN) * U + (size_t)(h & 3) * 256;
    float* C = g_att + (size_t)z * TLEN * TLEN + m0 * TLEN + n0;
    gemm_core<8, 0, false>(g_Qh + off + m0 * U, g_Ql + off + m0 * U, U,
                           g_Kh + off + n0 * U, g_Kl + off + n0 * U, U,
                           0.0625f, nullptr, C, nullptr, nullptr, TLEN);
}

__global__ void __launch_bounds__(256) k_attv()
{
    const int z = blockIdx.z;
    const int b = z >> 4, h = (z >> 1) & 7, n = z & 1;
    const size_t m0 = (size_t)blockIdx.y * 128;
    const size_t aoff = (size_t)(b * HEADS + h) * TLEN * TLEN + m0 * TLEN;
    const size_t boff = (size_t)(b * NCHAN + n) * TLEN * U + (size_t)h * DK * TLEN;
    const size_t coff = ((size_t)(b * NCHAN + n) * TLEN + m0) * U + (size_t)h * DK;
    gemm_core<32, 1, false>(g_atth + aoff, g_attl + aoff, TLEN,
                            g_Vth + boff,  g_Vtl + boff,  TLEN,
                            1.0f, nullptr, nullptr,
                            g_aoh + coff, g_aol + coff, U);
}

// ---------------- Conversion / softmax kernels ----------------
__global__ void __launch_bounds__(256) split_kernel(const float* __restrict__ src, int sel)
{
    __nv_bfloat16 *h, *l;
    switch (sel) {
        case 0: h = g_xh;  l = g_xl;  break;
        case 1: h = g_Wqh; l = g_Wql; break;
        case 2: h = g_Wkh; l = g_Wkl; break;
        case 3: h = g_Wvh; l = g_Wvl; break;
        default: h = g_Woh; l = g_Wol; break;
    }
    const size_t i = (size_t)blockIdx.x * 256 + threadIdx.x;
    float4 v = ((const float4*)src)[i];
    __nv_bfloat16 h0, l0, h1, l1, h2, l2, h3, l3;
    split1(v.x, h0, l0); split1(v.y, h1, l1);
    split1(v.z, h2, l2); split1(v.w, h3, l3);
    ((__nv_bfloat162*)(h + i * 4))[0] = __nv_bfloat162(h0, h1);
    ((__nv_bfloat162*)(h + i * 4))[1] = __nv_bfloat162(h2, h3);
    ((__nv_bfloat162*)(l + i * 4))[0] = __nv_bfloat162(l0, l1);
    ((__nv_bfloat162*)(l + i * 4))[1] = __nv_bfloat162(l2, l3);
}

// Transpose + split V per (b,n): Vt[d][s] = V[s][d]
__global__ void vtrans_kernel()
{
    __shared__ float tile[32][33];
    const int z = blockIdx.z;
    const int d0 = blockIdx.x * 32, s0 = blockIdx.y * 32;
    const float* src = g_V + (size_t)z * TLEN * U;
    tile[threadIdx.y][threadIdx.x] = src[(size_t)(s0 + threadIdx.y) * U + d0 + threadIdx.x];
    __syncthreads();
    float v = tile[threadIdx.x][threadIdx.y];       // = V[s0+tx][d0+ty]
    const size_t o = (size_t)z * TLEN * U + (size_t)(d0 + threadIdx.y) * TLEN + s0 + threadIdx.x;
    __nv_bfloat16 hh, ll;
    split1(v, hh, ll);
    g_Vth[o] = hh; g_Vtl[o] = ll;
}

__global__ void __launch_bounds__(256) softmax_kernel()
{
    const size_t row = blockIdx.x;
    const float4* p = (const float4*)(g_att + row * TLEN);
    const int tid = threadIdx.x;

    float4 x = p[tid];
    float m = fmaxf(fmaxf(x.x, x.y), fmaxf(x.z, x.w));
#pragma unroll
    for (int o = 16; o; o >>= 1) m = fmaxf(m, __shfl_xor_sync(0xffffffffu, m, o));
    __shared__ float rmax[8], rsum[8];
    if ((tid & 31) == 0) rmax[tid >> 5] = m;
    __syncthreads();
    float bm = fmaxf(fmaxf(fmaxf(rmax[0], rmax[1]), fmaxf(rmax[2], rmax[3])),
                     fmaxf(fmaxf(rmax[4], rmax[5]), fmaxf(rmax[6], rmax[7])));
    float e0 = __expf(x.x - bm), e1 = __expf(x.y - bm);
    float e2 = __expf(x.z - bm), e3 = __expf(x.w - bm);
    float s = e0 + e1 + e2 + e3;
#pragma unroll
    for (int o = 16; o; o >>= 1) s += __shfl_xor_sync(0xffffffffu, s, o);
    if ((tid & 31) == 0) rsum[tid >> 5] = s;
    __syncthreads();
    float inv = 1.0f / (rsum[0] + rsum[1] + rsum[2] + rsum[3]
                      + rsum[4] + rsum[5] + rsum[6] + rsum[7]);

    const size_t base = row * TLEN + (size_t)tid * 4;
    __nv_bfloat16 h0, l0, h1, l1, h2, l2, h3, l3;
    split1(e0 * inv, h0, l0); split1(e1 * inv, h1, l1);
    split1(e2 * inv, h2, l2); split1(e3 * inv, h3, l3);
    ((__nv_bfloat162*)(g_atth + base))[0] = __nv_bfloat162(h0, h1);
    ((__nv_bfloat162*)(g_atth + base))[1] = __nv_bfloat162(h2, h3);
    ((__nv_bfloat162*)(g_attl + base))[0] = __nv_bfloat162(l0, l1);
    ((__nv_bfloat162*)(g_attl + base))[1] = __nv_bfloat162(l2, l3);
}

// ---------------- Launch ----------------
extern "C" void kernel_launch(void* const* d_in, const int* in_sizes, int n_in,
                              void* d_out, int out_size)
{
    const float* x  = (const float*)d_in[0];
    const float* Wq = (const float*)d_in[2];
    const float* bq = (const float*)d_in[3];
    const float* Wk = (const float*)d_in[4];
    const float* bk = (const float*)d_in[5];
    const float* Wv = (const float*)d_in[6];
    const float* bv = (const float*)d_in[7];
    const float* Wo = (const float*)d_in[8];
    const float* bo = (const float*)d_in[9];
    float* out = (float*)d_out;

    cudaFuncSetAttribute(k_qkv,    cudaFuncAttributeMaxDynamicSharedMemorySize, SMEM_BYTES);
    cudaFuncSetAttribute(k_out,    cudaFuncAttributeMaxDynamicSharedMemorySize, SMEM_BYTES);
    cudaFuncSetAttribute(k_scores, cudaFuncAttributeMaxDynamicSharedMemorySize, SMEM_BYTES);
    cudaFuncSetAttribute(k_attv,   cudaFuncAttributeMaxDynamicSharedMemorySize, SMEM_BYTES);

    split_kernel<<<MS / 1024, 256>>>(x, 0);
    split_kernel<<<(U * U) / 1024, 256>>>(Wq, 1);
    split_kernel<<<(U * U) / 1024, 256>>>(Wk, 2);
    split_kernel<<<(U * U) / 1024, 256>>>(Wv, 3);
    split_kernel<<<(U * U) / 1024, 256>>>(Wo, 4);

    k_qkv<<<dim3(U / 128, MROWS / 128, 3), 256, SMEM_BYTES>>>(bq, bk, bv);

    vtrans_kernel<<<dim3(32, 32, BATCH * NCHAN), dim3(32, 32)>>>();

    k_scores<<<dim3(8, 8, BATCH * HEADS), 256, SMEM_BYTES>>>();

    softmax_kernel<<<BATCH * HEADS * TLEN, 256>>>();

    k_attv<<<dim3(1, 8, BATCH * HEADS * NCHAN), 256, SMEM_BYTES>>>();

    k_out<<<dim3(U / 128, MROWS / 128), 256, SMEM_BYTES>>>(bo, out);
}